// round 4
// baseline (speedup 1.0000x reference)
#include <cuda_runtime.h>
#include <cuda_fp16.h>

// Problem constants (fixed by setup_inputs): B=8, L=K=2048, D=32, SIGMA=1, EPS=1, 10 iters.
#define BB 8
#define NN 2048
#define DD 32
#define TOT (BB * NN)
#define MAT_ELEMS ((size_t)BB * NN * NN)
#define NTILES 32                    // 2048/64
#define SYMT (NTILES * (NTILES + 1) / 2)   // 528 lower-triangle tiles

// ---------------- device scratch (no runtime allocation allowed) ----------------
static __device__ __half g_Hxx[MAT_ELEMS];   // lower triangle only (tile granularity)
static __device__ __half g_Hyx[MAT_ELEMS];   // full, rows = y index
static __device__ __half g_Hyy[MAT_ELEMS];   // lower triangle only
static __device__ float g_nx[TOT], g_ny[TOT];
static __device__ float g_fxx[TOT], g_fyx[TOT], g_fxy[TOT], g_fyy[TOT];
static __device__ float g_w0[TOT], g_w1[TOT], g_w3[TOT];
static __device__ float g_S0[TOT], g_S1[TOT], g_S2[TOT], g_S3[TOT];

// ---------------- kernels ----------------

// Squared norms + zero-init potentials.
__global__ __launch_bounds__(256) void k_norms(const float* __restrict__ x,
                                               const float* __restrict__ y) {
    int i = blockIdx.x * 256 + threadIdx.x;
    if (i >= TOT) return;
    const float* xr = x + (size_t)i * DD;
    const float* yr = y + (size_t)i * DD;
    float sx = 0.f, sy = 0.f;
#pragma unroll
    for (int d = 0; d < DD; d++) {
        sx = fmaf(xr[d], xr[d], sx);
        sy = fmaf(yr[d], yr[d], sy);
    }
    g_nx[i] = sx;
    g_ny[i] = sy;
    g_fxx[i] = 0.f; g_fyx[i] = 0.f; g_fxy[i] = 0.f; g_fyy[i] = 0.f;
}

// Build H[b][r][c] = exp(exp(-max(nr+nc-2*dot,0)/2)), fp16.
// 64x64 tile/block. sym!=0: only lower-triangle tile blocks write (no mirror —
// the symmetric GEMV never reads the upper triangle).
__global__ __launch_bounds__(256) void k_build(int hsel, int sym,
                                               const float* __restrict__ Rm,
                                               const float* __restrict__ Cm,
                                               int rn, int cn) {
    int bx = blockIdx.x, by = blockIdx.y, b = blockIdx.z;
    if (sym && bx > by) return;
    __shared__ float srt[DD][68];
    __shared__ float sct[DD][68];

    int r0 = by * 64, c0 = bx * 64;
    const float* Rb = Rm + ((size_t)b * NN + r0) * DD;
    const float* Cb = Cm + ((size_t)b * NN + c0) * DD;
    for (int i = threadIdx.x; i < 64 * DD; i += 256) {
        int row = i >> 5, d = i & 31;
        srt[d][row] = Rb[i];
        sct[d][row] = Cb[i];
    }
    __syncthreads();

    int tx = threadIdx.x & 15, ty = threadIdx.x >> 4;
    float acc[4][4];
#pragma unroll
    for (int i = 0; i < 4; i++)
#pragma unroll
        for (int j = 0; j < 4; j++) acc[i][j] = 0.f;

#pragma unroll
    for (int d = 0; d < DD; d++) {
        float4 rv4 = *(const float4*)&srt[d][ty * 4];
        float4 cv4 = *(const float4*)&sct[d][tx * 4];
        float rv[4] = {rv4.x, rv4.y, rv4.z, rv4.w};
        float cv[4] = {cv4.x, cv4.y, cv4.z, cv4.w};
#pragma unroll
        for (int i = 0; i < 4; i++)
#pragma unroll
            for (int j = 0; j < 4; j++)
                acc[i][j] = fmaf(rv[i], cv[j], acc[i][j]);
    }

    const float* nRp = (rn ? g_ny : g_nx) + b * NN + r0;
    const float* nCp = (cn ? g_ny : g_nx) + b * NN + c0;
    float nr[4], ncv[4];
#pragma unroll
    for (int i = 0; i < 4; i++) nr[i] = nRp[ty * 4 + i];
#pragma unroll
    for (int j = 0; j < 4; j++) ncv[j] = nCp[tx * 4 + j];

    __half* H = (hsel == 0 ? g_Hxx : hsel == 1 ? g_Hyx : g_Hyy);
#pragma unroll
    for (int i = 0; i < 4; i++) {
        float o[4];
#pragma unroll
        for (int j = 0; j < 4; j++) {
            float dist = nr[i] + ncv[j] - 2.f * acc[i][j];
            float t = __expf(-0.5f * fmaxf(dist, 0.f));
            o[j] = __expf(t);
        }
        union { __half2 h2[2]; uint2 u; } cv;
        cv.h2[0] = __floats2half2_rn(o[0], o[1]);
        cv.h2[1] = __floats2half2_rn(o[2], o[3]);
        *(uint2*)&H[((size_t)b * NN + r0 + ty * 4 + i) * NN + c0 + tx * 4] = cv.u;
    }
}

// Per-iteration prep: apply all deferred epilogues (f = 0.5f - 0.5 log S) from
// the previous iteration's raw sums, compute weight vectors, zero accumulators.
__global__ __launch_bounds__(256) void k_prep(const float* __restrict__ a,
                                              const float* __restrict__ bw,
                                              int do_epi) {
    int i = blockIdx.x * 256 + threadIdx.x;
    if (i >= TOT) return;
    float fxx = g_fxx[i], fyx = g_fyx[i], fxy = g_fxy[i], fyy = g_fyy[i];
    if (do_epi) {
        fxx = 0.5f * fxx - 0.5f * __logf(g_S0[i]);
        fyx = 0.5f * fyx - 0.5f * __logf(g_S1[i]);
        fxy = 0.5f * fxy - 0.5f * __logf(g_S2[i]);
        fyy = 0.5f * fyy - 0.5f * __logf(g_S3[i]);
        g_fxx[i] = fxx; g_fyx[i] = fyx; g_fxy[i] = fxy; g_fyy[i] = fyy;
    }
    g_S0[i] = 0.f; g_S2[i] = 0.f; g_S3[i] = 0.f;    // atomic accumulators
    g_w0[i] = __expf(a[i] + fxx);    // Hxx sym GEMV
    g_w1[i] = __expf(a[i] + fxy);    // Hyx row GEMV (OLD fxy)
    g_w3[i] = __expf(bw[i] + fyy);   // Hyy sym GEMV
}

// Fused GEMV launch. blockIdx.x ranges:
//  [0, 528)        : symmetric tiles of Hxx -> S0 (atomic)
//  [528, 1056)     : symmetric tiles of Hyy -> S3 (atomic)
//  [1056, 1312)    : Hyx row GEMV (8 rows/block) -> S1 raw (direct store)
__global__ __launch_bounds__(256) void k_gemv(int /*unused*/) {
    __shared__ union {
        struct { __half tile[64][72]; float wI[64]; float wJ[64]; } s;
        float ws[NN];
    } sm;
    int bz = blockIdx.z;
    int bx = blockIdx.x;
    int tid = threadIdx.x;

    if (bx < 2 * SYMT) {
        // ---- symmetric tile GEMV ----
        int sel = bx >= SYMT;
        int t = bx - sel * SYMT;
        int I = (int)((sqrtf(8.f * (float)t + 1.f) - 1.f) * 0.5f);
        while ((I + 1) * (I + 2) / 2 <= t) I++;
        while (I * (I + 1) / 2 > t) I--;
        int J = t - I * (I + 1) / 2;       // I >= J

        const __half* H = sel ? g_Hyy : g_Hxx;
        const float* w = sel ? g_w3 : g_w0;
        float* S = (sel ? g_S3 : g_S0) + bz * NN;

        // load 64x64 fp16 tile (8 KB) into SMEM, padded stride 72 (16B aligned)
        const __half* Hb = H + ((size_t)bz * NN + I * 64) * NN + J * 64;
#pragma unroll
        for (int i = 0; i < 2; i++) {
            int idx = tid + i * 256;          // 512 uint4 total
            int r = idx >> 3, c16 = idx & 7;
            uint4 v = *(const uint4*)(Hb + (size_t)r * NN + c16 * 8);
            *(uint4*)&sm.s.tile[r][c16 * 8] = v;
        }
        if (tid < 64) sm.s.wI[tid] = w[bz * NN + I * 64 + tid];
        else if (tid < 128) sm.s.wJ[tid - 64] = w[bz * NN + J * 64 + tid - 64];
        __syncthreads();

        // row product: S[I*64 + r] += sum_c tile[r][c] * wJ[c]
        {
            int r = tid >> 2, q = tid & 3;
            const __half2* trow = (const __half2*)&sm.s.tile[r][q * 16];
            const float* wj = &sm.s.wJ[q * 16];
            float acc = 0.f;
#pragma unroll
            for (int i = 0; i < 8; i++) {
                float2 h = __half22float2(trow[i]);
                acc = fmaf(h.x, wj[2 * i], acc);
                acc = fmaf(h.y, wj[2 * i + 1], acc);
            }
            acc += __shfl_xor_sync(0xffffffffu, acc, 1);
            acc += __shfl_xor_sync(0xffffffffu, acc, 2);
            if (q == 0) atomicAdd(&S[I * 64 + r], acc);
        }
        // column product (off-diagonal only): S[J*64 + c] += sum_r tile[r][c] * wI[r]
        if (I != J) {
            int p = tid >> 6, c = tid & 63;
            float cacc = 0.f;
#pragma unroll
            for (int i = 0; i < 16; i++) {
                int r = p * 16 + i;
                cacc = fmaf(__half2float(sm.s.tile[r][c]), sm.s.wI[r], cacc);
            }
            atomicAdd(&S[J * 64 + c], cacc);
        }
    } else {
        // ---- Hyx row GEMV: 8 rows per block, w1 staged in SMEM ----
        int rb = bx - 2 * SYMT;            // 0..255
        int row0 = bz * 256 * 8 + rb * 8;  // global row base... careful: rows per batch = 2048
        // rows are per-batch: row index within batch:
        int rloc = rb * 8;
        const float4* wg = (const float4*)(g_w1 + bz * NN);
        float4* wsv = (float4*)sm.ws;
#pragma unroll
        for (int i = 0; i < 2; i++) wsv[i * 256 + tid] = wg[i * 256 + tid];
        __syncthreads();

        int warp = tid >> 5, lane = tid & 31;
        int row = rloc + warp;
        const uint4* hrow = (const uint4*)(g_Hyx + ((size_t)bz * NN + row) * NN);
        float acc0 = 0.f, acc1 = 0.f;
#pragma unroll
        for (int it = 0; it < 8; it++) {
            uint4 h = hrow[it * 32 + lane];
            const float* wp = &sm.ws[(it * 32 + lane) * 8];
            float4 wa = *(const float4*)wp;
            float4 wb = *(const float4*)(wp + 4);
            float2 h0 = __half22float2(*(const __half2*)&h.x);
            float2 h1 = __half22float2(*(const __half2*)&h.y);
            float2 h2 = __half22float2(*(const __half2*)&h.z);
            float2 h3 = __half22float2(*(const __half2*)&h.w);
            acc0 = fmaf(h0.x, wa.x, acc0);
            acc1 = fmaf(h0.y, wa.y, acc1);
            acc0 = fmaf(h1.x, wa.z, acc0);
            acc1 = fmaf(h1.y, wa.w, acc1);
            acc0 = fmaf(h2.x, wb.x, acc0);
            acc1 = fmaf(h2.y, wb.y, acc1);
            acc0 = fmaf(h3.x, wb.z, acc0);
            acc1 = fmaf(h3.y, wb.w, acc1);
        }
        float acc = acc0 + acc1;
#pragma unroll
        for (int o = 16; o; o >>= 1) acc += __shfl_xor_sync(0xffffffffu, acc, o);
        if (lane == 0) g_S1[bz * NN + row] = acc;   // raw; epilogue deferred
        (void)row0;
    }
}

// Column GEMV over g_Hyx: S2[b,l] += sum_k Hyx[b,k,l] * w2[b,k].
// Gauss-Seidel: w2 uses the NEW fyx, recomputed locally from raw S1.
// fin: use stored fyx directly (no 11th update).
__global__ __launch_bounds__(256) void k_gemv_cols(const float* __restrict__ bw, int fin) {
    __shared__ float ws[64];
    int b = blockIdx.z, ks = blockIdx.x;
    int tid = threadIdx.x;
    if (tid < 64) {
        int k = b * NN + ks * 64 + tid;
        float fyx = g_fyx[k];
        if (!fin) fyx = 0.5f * fyx - 0.5f * __logf(g_S1[k]);
        ws[tid] = __expf(bw[k] + fyx);
    }
    __syncthreads();

    const uint4* Hb = (const uint4*)(g_Hyx + ((size_t)b * NN + ks * 64) * NN);
    float acc[8];
#pragma unroll
    for (int j = 0; j < 8; j++) acc[j] = 0.f;
#pragma unroll 4
    for (int k = 0; k < 64; k++) {
        float wk = ws[k];
        uint4 h = Hb[(size_t)k * (NN / 8) + tid];
        float2 h0 = __half22float2(*(const __half2*)&h.x);
        float2 h1 = __half22float2(*(const __half2*)&h.y);
        float2 h2 = __half22float2(*(const __half2*)&h.z);
        float2 h3 = __half22float2(*(const __half2*)&h.w);
        acc[0] = fmaf(h0.x, wk, acc[0]);
        acc[1] = fmaf(h0.y, wk, acc[1]);
        acc[2] = fmaf(h1.x, wk, acc[2]);
        acc[3] = fmaf(h1.y, wk, acc[3]);
        acc[4] = fmaf(h2.x, wk, acc[4]);
        acc[5] = fmaf(h2.y, wk, acc[5]);
        acc[6] = fmaf(h3.x, wk, acc[6]);
        acc[7] = fmaf(h3.y, wk, acc[7]);
    }
    float* S = g_S2 + b * NN + 8 * tid;
#pragma unroll
    for (int j = 0; j < 8; j++) atomicAdd(S + j, acc[j]);
}

// res[b] = sum_l (fe_xy - fe_xx) e^a + sum_k (fe_yx - fe_yy) e^b, fe_* = -log S_*.
__global__ __launch_bounds__(256) void k_reduce(const float* __restrict__ a,
                                                const float* __restrict__ bw,
                                                float* __restrict__ out) {
    int b = blockIdx.x;
    float acc = 0.f;
    for (int i = threadIdx.x; i < NN; i += 256) {
        int idx = b * NN + i;
        float fexx = -__logf(g_S0[idx]);
        float feyx = -__logf(g_S1[idx]);
        float fexy = -__logf(g_S2[idx]);
        float feyy = -__logf(g_S3[idx]);
        acc += (fexy - fexx) * __expf(a[idx]) + (feyx - feyy) * __expf(bw[idx]);
    }
    __shared__ float red[256];
    red[threadIdx.x] = acc;
    __syncthreads();
    for (int s = 128; s; s >>= 1) {
        if (threadIdx.x < s) red[threadIdx.x] += red[threadIdx.x + s];
        __syncthreads();
    }
    if (threadIdx.x == 0) out[b] = red[0];
}

// ---------------- launch ----------------
extern "C" void kernel_launch(void* const* d_in, const int* in_sizes, int n_in,
                              void* d_out, int out_size) {
    const float* x = (const float*)d_in[0];
    const float* a = (const float*)d_in[1];
    const float* y = (const float*)d_in[2];
    const float* b = (const float*)d_in[3];
    float* out = (float*)d_out;

    const int SMALL_BLOCKS = TOT / 256;              // 64
    dim3 buildGrid(NTILES, NTILES, BB);              // (32, 32, 8)
    dim3 gemvGrid(2 * SYMT + 256, 1, BB);            // (1312, 1, 8)
    dim3 colsGrid(32, 1, BB);

    k_norms<<<SMALL_BLOCKS, 256>>>(x, y);

    k_build<<<buildGrid, 256>>>(0, 1, x, x, 0, 0);   // Hxx lower triangle
    k_build<<<buildGrid, 256>>>(1, 0, y, x, 1, 0);   // Hyx full
    k_build<<<buildGrid, 256>>>(2, 1, y, y, 1, 1);   // Hyy lower triangle

    // iters 0..9: Sinkhorn; iter 10: final extrapolation (raw sums).
    for (int it = 0; it <= 10; it++) {
        int fin = (it == 10);
        k_prep<<<SMALL_BLOCKS, 256>>>(a, b, it > 0);
        k_gemv<<<gemvGrid, 256>>>(0);
        k_gemv_cols<<<colsGrid, 256>>>(b, fin);
    }

    k_reduce<<<BB, 256>>>(a, b, out);
}

// round 5
// speedup vs baseline: 1.0015x; 1.0015x over previous
#include <cuda_runtime.h>
#include <cuda_fp16.h>

// Problem constants: B=8, L=K=2048, D=32, SIGMA=1, EPS=1, 10 iters.
#define BB 8
#define NN 2048
#define DD 32
#define TOT (BB * NN)
#define MAT_ELEMS ((size_t)BB * NN * NN)
#define NTILES 32                          // 2048/64
#define SYMT (NTILES * (NTILES + 1) / 2)   // 528 lower-triangle tiles
#define TILE_ELEMS 4096                    // 64*64
#define SYM_ELEMS ((size_t)BB * SYMT * TILE_ELEMS)

// ---------------- device scratch ----------------
static __device__ __half g_Hxx[SYM_ELEMS];   // tiled lower-triangle, 8KB/tile contiguous
static __device__ __half g_Hyy[SYM_ELEMS];   // tiled lower-triangle
static __device__ __half g_Hyx[MAT_ELEMS];   // full, row-major, rows = y index
static __device__ float g_nx[TOT], g_ny[TOT];
static __device__ float g_fxx[TOT], g_fyx[TOT], g_fxy[TOT], g_fyy[TOT];
static __device__ float g_w0[TOT], g_w1[TOT], g_w3[TOT];
static __device__ float g_S0[TOT], g_S1[TOT], g_S2[TOT], g_S3[TOT];

// ---------------- kernels ----------------

__global__ __launch_bounds__(256) void k_norms(const float* __restrict__ x,
                                               const float* __restrict__ y) {
    int i = blockIdx.x * 256 + threadIdx.x;
    if (i >= TOT) return;
    const float* xr = x + (size_t)i * DD;
    const float* yr = y + (size_t)i * DD;
    float sx = 0.f, sy = 0.f;
#pragma unroll
    for (int d = 0; d < DD; d++) {
        sx = fmaf(xr[d], xr[d], sx);
        sy = fmaf(yr[d], yr[d], sy);
    }
    g_nx[i] = sx;
    g_ny[i] = sy;
    g_fxx[i] = 0.f; g_fyx[i] = 0.f; g_fxy[i] = 0.f; g_fyy[i] = 0.f;
}

// Build H = exp(exp(-max(nr+nc-2*dot,0)/2)) fp16.
// sym!=0: grid covers only lower-triangle tiles; output to tiled layout.
// sym==0: full row-major output (Hyx).
__global__ __launch_bounds__(256) void k_build(int hsel, int sym,
                                               const float* __restrict__ Rm,
                                               const float* __restrict__ Cm,
                                               int rn, int cn) {
    int bx = blockIdx.x, by = blockIdx.y, b = blockIdx.z;
    if (sym && bx > by) return;
    __shared__ float srt[DD][68];
    __shared__ float sct[DD][68];

    int r0 = by * 64, c0 = bx * 64;
    const float* Rb = Rm + ((size_t)b * NN + r0) * DD;
    const float* Cb = Cm + ((size_t)b * NN + c0) * DD;
    for (int i = threadIdx.x; i < 64 * DD; i += 256) {
        int row = i >> 5, d = i & 31;
        srt[d][row] = Rb[i];
        sct[d][row] = Cb[i];
    }
    __syncthreads();

    int tx = threadIdx.x & 15, ty = threadIdx.x >> 4;
    float acc[4][4];
#pragma unroll
    for (int i = 0; i < 4; i++)
#pragma unroll
        for (int j = 0; j < 4; j++) acc[i][j] = 0.f;

#pragma unroll
    for (int d = 0; d < DD; d++) {
        float4 rv4 = *(const float4*)&srt[d][ty * 4];
        float4 cv4 = *(const float4*)&sct[d][tx * 4];
        float rv[4] = {rv4.x, rv4.y, rv4.z, rv4.w};
        float cv[4] = {cv4.x, cv4.y, cv4.z, cv4.w};
#pragma unroll
        for (int i = 0; i < 4; i++)
#pragma unroll
            for (int j = 0; j < 4; j++)
                acc[i][j] = fmaf(rv[i], cv[j], acc[i][j]);
    }

    const float* nRp = (rn ? g_ny : g_nx) + b * NN + r0;
    const float* nCp = (cn ? g_ny : g_nx) + b * NN + c0;
    float nr[4], ncv[4];
#pragma unroll
    for (int i = 0; i < 4; i++) nr[i] = nRp[ty * 4 + i];
#pragma unroll
    for (int j = 0; j < 4; j++) ncv[j] = nCp[tx * 4 + j];

    // output base pointer
    __half* outp;
    size_t rstride;
    if (sym) {
        int t = by * (by + 1) / 2 + bx;    // I=by >= J=bx
        __half* H = (hsel == 0 ? g_Hxx : g_Hyy);
        outp = H + ((size_t)b * SYMT + t) * TILE_ELEMS;
        rstride = 64;
    } else {
        outp = g_Hyx + ((size_t)b * NN + r0) * NN + c0;
        rstride = NN;
    }

#pragma unroll
    for (int i = 0; i < 4; i++) {
        float o[4];
#pragma unroll
        for (int j = 0; j < 4; j++) {
            float dist = nr[i] + ncv[j] - 2.f * acc[i][j];
            float t = __expf(-0.5f * fmaxf(dist, 0.f));
            o[j] = __expf(t);
        }
        union { __half2 h2[2]; uint2 u; } cv;
        cv.h2[0] = __floats2half2_rn(o[0], o[1]);
        cv.h2[1] = __floats2half2_rn(o[2], o[3]);
        *(uint2*)&outp[(size_t)(ty * 4 + i) * rstride + tx * 4] = cv.u;
    }
}

// Per-iteration prep: deferred epilogues + weights + zero atomic accumulators.
__global__ __launch_bounds__(256) void k_prep(const float* __restrict__ a,
                                              const float* __restrict__ bw,
                                              int do_epi) {
    int i = blockIdx.x * 256 + threadIdx.x;
    if (i >= TOT) return;
    float fxx = g_fxx[i], fyx = g_fyx[i], fxy = g_fxy[i], fyy = g_fyy[i];
    if (do_epi) {
        fxx = 0.5f * fxx - 0.5f * __logf(g_S0[i]);
        fyx = 0.5f * fyx - 0.5f * __logf(g_S1[i]);
        fxy = 0.5f * fxy - 0.5f * __logf(g_S2[i]);
        fyy = 0.5f * fyy - 0.5f * __logf(g_S3[i]);
        g_fxx[i] = fxx; g_fyx[i] = fyx; g_fxy[i] = fxy; g_fyy[i] = fyy;
    }
    g_S0[i] = 0.f; g_S2[i] = 0.f; g_S3[i] = 0.f;
    g_w0[i] = __expf(a[i] + fxx);    // Hxx sym GEMV
    g_w1[i] = __expf(a[i] + fxy);    // Hyx row GEMV (OLD fxy)
    g_w3[i] = __expf(bw[i] + fyy);   // Hyy sym GEMV
}

// Fused GEMV. blockIdx.x:
//  [0, 528)      : Hxx symmetric tiles -> S0 (atomic)
//  [528, 1056)   : Hyy symmetric tiles -> S3 (atomic)
//  [1056, 1312)  : Hyx row GEMV (8 rows/block) -> S1 raw
__global__ __launch_bounds__(256) void k_gemv() {
    __shared__ union {
        struct { __half tile[64][72]; float wI[64]; float wJ[64]; } s;
        float ws[NN];
    } sm;
    int bz = blockIdx.z;
    int bx = blockIdx.x;
    int tid = threadIdx.x;

    if (bx < 2 * SYMT) {
        // ---- symmetric tile GEMV (contiguous 8KB tile load) ----
        int sel = bx >= SYMT;
        int t = bx - sel * SYMT;
        int I = (int)((sqrtf(8.f * (float)t + 1.f) - 1.f) * 0.5f);
        while ((I + 1) * (I + 2) / 2 <= t) I++;
        while (I * (I + 1) / 2 > t) I--;
        int J = t - I * (I + 1) / 2;       // I >= J

        const __half* Hb = (sel ? g_Hyy : g_Hxx) + ((size_t)bz * SYMT + t) * TILE_ELEMS;
        const float* w = sel ? g_w3 : g_w0;
        float* S = (sel ? g_S3 : g_S0) + bz * NN;

        const uint4* Hv = (const uint4*)Hb;        // 512 uint4 = 8KB contiguous
#pragma unroll
        for (int i = 0; i < 2; i++) {
            int idx = tid + i * 256;
            int r = idx >> 3, c = (idx & 7) * 8;
            *(uint4*)&sm.s.tile[r][c] = Hv[idx];
        }
        if (tid < 64) sm.s.wI[tid] = w[bz * NN + I * 64 + tid];
        else if (tid < 128) sm.s.wJ[tid - 64] = w[bz * NN + J * 64 + tid - 64];
        __syncthreads();

        // row product: S[I*64+r] += sum_c tile[r][c]*wJ[c]  (4 threads/row)
        {
            int r = tid >> 2, q = tid & 3;
            const __half2* trow = (const __half2*)&sm.s.tile[r][q * 16];
            const float* wj = &sm.s.wJ[q * 16];
            float acc = 0.f;
#pragma unroll
            for (int i = 0; i < 8; i++) {
                float2 h = __half22float2(trow[i]);
                acc = fmaf(h.x, wj[2 * i], acc);
                acc = fmaf(h.y, wj[2 * i + 1], acc);
            }
            acc += __shfl_xor_sync(0xffffffffu, acc, 1);
            acc += __shfl_xor_sync(0xffffffffu, acc, 2);
            if (q == 0) atomicAdd(&S[I * 64 + r], acc);
        }
        // column product (off-diagonal): S[J*64+c] += sum_r tile[r][c]*wI[r]
        if (I != J) {
            int p = tid >> 6, c = tid & 63;
            float cacc = 0.f;
#pragma unroll
            for (int i = 0; i < 16; i++) {
                int r = p * 16 + i;
                cacc = fmaf(__half2float(sm.s.tile[r][c]), sm.s.wI[r], cacc);
            }
            atomicAdd(&S[J * 64 + c], cacc);
        }
    } else {
        // ---- Hyx row GEMV: 8 rows/block, w1 staged in SMEM ----
        int rloc = (bx - 2 * SYMT) * 8;
        const float4* wg = (const float4*)(g_w1 + bz * NN);
        float4* wsv = (float4*)sm.ws;
#pragma unroll
        for (int i = 0; i < 2; i++) wsv[i * 256 + tid] = wg[i * 256 + tid];
        __syncthreads();

        int warp = tid >> 5, lane = tid & 31;
        int row = rloc + warp;
        const uint4* hrow = (const uint4*)(g_Hyx + ((size_t)bz * NN + row) * NN);
        float acc0 = 0.f, acc1 = 0.f;
#pragma unroll
        for (int it = 0; it < 8; it++) {
            uint4 h = hrow[it * 32 + lane];
            const float* wp = &sm.ws[(it * 32 + lane) * 8];
            float4 wa = *(const float4*)wp;
            float4 wb = *(const float4*)(wp + 4);
            float2 h0 = __half22float2(*(const __half2*)&h.x);
            float2 h1 = __half22float2(*(const __half2*)&h.y);
            float2 h2 = __half22float2(*(const __half2*)&h.z);
            float2 h3 = __half22float2(*(const __half2*)&h.w);
            acc0 = fmaf(h0.x, wa.x, acc0);
            acc1 = fmaf(h0.y, wa.y, acc1);
            acc0 = fmaf(h1.x, wa.z, acc0);
            acc1 = fmaf(h1.y, wa.w, acc1);
            acc0 = fmaf(h2.x, wb.x, acc0);
            acc1 = fmaf(h2.y, wb.y, acc1);
            acc0 = fmaf(h3.x, wb.z, acc0);
            acc1 = fmaf(h3.y, wb.w, acc1);
        }
        float acc = acc0 + acc1;
#pragma unroll
        for (int o = 16; o; o >>= 1) acc += __shfl_xor_sync(0xffffffffu, acc, o);
        if (lane == 0) g_S1[bz * NN + row] = acc;   // raw; epilogue deferred
    }
}

// Column GEMV over g_Hyx: S2[b,l] += sum_k Hyx[b,k,l]*w2[b,k].
// Gauss-Seidel: w2 uses NEW fyx, recomputed locally from raw S1.
__global__ __launch_bounds__(256) void k_gemv_cols(const float* __restrict__ bw, int fin) {
    __shared__ float ws[64];
    int b = blockIdx.z, ks = blockIdx.x;
    int tid = threadIdx.x;
    if (tid < 64) {
        int k = b * NN + ks * 64 + tid;
        float fyx = g_fyx[k];
        if (!fin) fyx = 0.5f * fyx - 0.5f * __logf(g_S1[k]);
        ws[tid] = __expf(bw[k] + fyx);
    }
    __syncthreads();

    const uint4* Hb = (const uint4*)(g_Hyx + ((size_t)b * NN + ks * 64) * NN);
    float acc[8];
#pragma unroll
    for (int j = 0; j < 8; j++) acc[j] = 0.f;
#pragma unroll 4
    for (int k = 0; k < 64; k++) {
        float wk = ws[k];
        uint4 h = Hb[(size_t)k * (NN / 8) + tid];
        float2 h0 = __half22float2(*(const __half2*)&h.x);
        float2 h1 = __half22float2(*(const __half2*)&h.y);
        float2 h2 = __half22float2(*(const __half2*)&h.z);
        float2 h3 = __half22float2(*(const __half2*)&h.w);
        acc[0] = fmaf(h0.x, wk, acc[0]);
        acc[1] = fmaf(h0.y, wk, acc[1]);
        acc[2] = fmaf(h1.x, wk, acc[2]);
        acc[3] = fmaf(h1.y, wk, acc[3]);
        acc[4] = fmaf(h2.x, wk, acc[4]);
        acc[5] = fmaf(h2.y, wk, acc[5]);
        acc[6] = fmaf(h3.x, wk, acc[6]);
        acc[7] = fmaf(h3.y, wk, acc[7]);
    }
    float* S = g_S2 + b * NN + 8 * tid;
#pragma unroll
    for (int j = 0; j < 8; j++) atomicAdd(S + j, acc[j]);
}

// res[b] = sum_l (fe_xy - fe_xx) e^a + sum_k (fe_yx - fe_yy) e^b, fe_* = -log S_*.
__global__ __launch_bounds__(256) void k_reduce(const float* __restrict__ a,
                                                const float* __restrict__ bw,
                                                float* __restrict__ out) {
    int b = blockIdx.x;
    float acc = 0.f;
    for (int i = threadIdx.x; i < NN; i += 256) {
        int idx = b * NN + i;
        float fexx = -__logf(g_S0[idx]);
        float feyx = -__logf(g_S1[idx]);
        float fexy = -__logf(g_S2[idx]);
        float feyy = -__logf(g_S3[idx]);
        acc += (fexy - fexx) * __expf(a[idx]) + (feyx - feyy) * __expf(bw[idx]);
    }
    __shared__ float red[256];
    red[threadIdx.x] = acc;
    __syncthreads();
    for (int s = 128; s; s >>= 1) {
        if (threadIdx.x < s) red[threadIdx.x] += red[threadIdx.x + s];
        __syncthreads();
    }
    if (threadIdx.x == 0) out[b] = red[0];
}

// ---------------- launch ----------------
extern "C" void kernel_launch(void* const* d_in, const int* in_sizes, int n_in,
                              void* d_out, int out_size) {
    const float* x = (const float*)d_in[0];
    const float* a = (const float*)d_in[1];
    const float* y = (const float*)d_in[2];
    const float* b = (const float*)d_in[3];
    float* out = (float*)d_out;

    const int SMALL_BLOCKS = TOT / 256;
    dim3 buildGrid(NTILES, NTILES, BB);
    dim3 gemvGrid(2 * SYMT + 256, 1, BB);
    dim3 colsGrid(32, 1, BB);

    k_norms<<<SMALL_BLOCKS, 256>>>(x, y);

    k_build<<<buildGrid, 256>>>(0, 1, x, x, 0, 0);   // Hxx tiled lower-tri
    k_build<<<buildGrid, 256>>>(1, 0, y, x, 1, 0);   // Hyx full row-major
    k_build<<<buildGrid, 256>>>(2, 1, y, y, 1, 1);   // Hyy tiled lower-tri

    for (int it = 0; it <= 10; it++) {
        int fin = (it == 10);
        k_prep<<<SMALL_BLOCKS, 256>>>(a, b, it > 0);
        k_gemv<<<gemvGrid, 256>>>();
        k_gemv_cols<<<colsGrid, 256>>>(b, fin);
    }

    k_reduce<<<BB, 256>>>(a, b, out);
}

// round 6
// speedup vs baseline: 1.0435x; 1.0419x over previous
#include <cuda_runtime.h>
#include <cuda_fp16.h>

// Problem constants: B=8, L=K=2048, D=32, SIGMA=1, EPS=1, 10 iters.
#define BB 8
#define NN 2048
#define DD 32
#define TOT (BB * NN)
#define MAT_ELEMS ((size_t)BB * NN * NN)
#define NTILES 32                          // 2048/64
#define SYMT (NTILES * (NTILES + 1) / 2)   // 528 lower-triangle tiles
#define TILE_ELEMS 4096                    // 64*64
#define SYM_ELEMS ((size_t)BB * SYMT * TILE_ELEMS)
#define NGRP 272                           // sum over I of ceil((I+1)/2)

// ---------------- device scratch ----------------
static __device__ __half g_Hxx[SYM_ELEMS];   // tiled lower-triangle, 8KB/tile contiguous
static __device__ __half g_Hyy[SYM_ELEMS];   // tiled lower-triangle
static __device__ __half g_Hyx[MAT_ELEMS];   // full, row-major, rows = y index
static __device__ float g_nx[TOT], g_ny[TOT];
static __device__ float g_fxx[TOT], g_fyx[TOT], g_fxy[TOT], g_fyy[TOT];
static __device__ float g_w0[TOT], g_w1[TOT], g_w3[TOT];
static __device__ float g_S0[TOT], g_S1[TOT], g_S2[TOT], g_S3[TOT];

// ---------------- kernels ----------------

__global__ __launch_bounds__(256) void k_norms(const float* __restrict__ x,
                                               const float* __restrict__ y) {
    int i = blockIdx.x * 256 + threadIdx.x;
    if (i >= TOT) return;
    const float* xr = x + (size_t)i * DD;
    const float* yr = y + (size_t)i * DD;
    float sx = 0.f, sy = 0.f;
#pragma unroll
    for (int d = 0; d < DD; d++) {
        sx = fmaf(xr[d], xr[d], sx);
        sy = fmaf(yr[d], yr[d], sy);
    }
    g_nx[i] = sx;
    g_ny[i] = sy;
    g_fxx[i] = 0.f; g_fyx[i] = 0.f; g_fxy[i] = 0.f; g_fyy[i] = 0.f;
}

// Build H = exp(exp(-max(nr+nc-2*dot,0)/2)) fp16.
// sym!=0: lower-triangle tiles only, tiled contiguous output. sym==0: row-major.
__global__ __launch_bounds__(256) void k_build(int hsel, int sym,
                                               const float* __restrict__ Rm,
                                               const float* __restrict__ Cm,
                                               int rn, int cn) {
    int bx = blockIdx.x, by = blockIdx.y, b = blockIdx.z;
    if (sym && bx > by) return;
    __shared__ float srt[DD][68];
    __shared__ float sct[DD][68];

    int r0 = by * 64, c0 = bx * 64;
    const float* Rb = Rm + ((size_t)b * NN + r0) * DD;
    const float* Cb = Cm + ((size_t)b * NN + c0) * DD;
    for (int i = threadIdx.x; i < 64 * DD; i += 256) {
        int row = i >> 5, d = i & 31;
        srt[d][row] = Rb[i];
        sct[d][row] = Cb[i];
    }
    __syncthreads();

    int tx = threadIdx.x & 15, ty = threadIdx.x >> 4;
    float acc[4][4];
#pragma unroll
    for (int i = 0; i < 4; i++)
#pragma unroll
        for (int j = 0; j < 4; j++) acc[i][j] = 0.f;

#pragma unroll
    for (int d = 0; d < DD; d++) {
        float4 rv4 = *(const float4*)&srt[d][ty * 4];
        float4 cv4 = *(const float4*)&sct[d][tx * 4];
        float rv[4] = {rv4.x, rv4.y, rv4.z, rv4.w};
        float cv[4] = {cv4.x, cv4.y, cv4.z, cv4.w};
#pragma unroll
        for (int i = 0; i < 4; i++)
#pragma unroll
            for (int j = 0; j < 4; j++)
                acc[i][j] = fmaf(rv[i], cv[j], acc[i][j]);
    }

    const float* nRp = (rn ? g_ny : g_nx) + b * NN + r0;
    const float* nCp = (cn ? g_ny : g_nx) + b * NN + c0;
    float nr[4], ncv[4];
#pragma unroll
    for (int i = 0; i < 4; i++) nr[i] = nRp[ty * 4 + i];
#pragma unroll
    for (int j = 0; j < 4; j++) ncv[j] = nCp[tx * 4 + j];

    __half* outp;
    size_t rstride;
    if (sym) {
        int t = by * (by + 1) / 2 + bx;
        __half* H = (hsel == 0 ? g_Hxx : g_Hyy);
        outp = H + ((size_t)b * SYMT + t) * TILE_ELEMS;
        rstride = 64;
    } else {
        outp = g_Hyx + ((size_t)b * NN + r0) * NN + c0;
        rstride = NN;
    }

#pragma unroll
    for (int i = 0; i < 4; i++) {
        float o[4];
#pragma unroll
        for (int j = 0; j < 4; j++) {
            float dist = nr[i] + ncv[j] - 2.f * acc[i][j];
            float t = __expf(-0.5f * fmaxf(dist, 0.f));
            o[j] = __expf(t);
        }
        union { __half2 h2[2]; uint2 u; } cv;
        cv.h2[0] = __floats2half2_rn(o[0], o[1]);
        cv.h2[1] = __floats2half2_rn(o[2], o[3]);
        *(uint2*)&outp[(size_t)(ty * 4 + i) * rstride + tx * 4] = cv.u;
    }
}

// Per-iteration prep: deferred epilogues + weights + zero atomic accumulators.
__global__ __launch_bounds__(256) void k_prep(const float* __restrict__ a,
                                              const float* __restrict__ bw,
                                              int do_epi) {
    int i = blockIdx.x * 256 + threadIdx.x;
    if (i >= TOT) return;
    float fxx = g_fxx[i], fyx = g_fyx[i], fxy = g_fxy[i], fyy = g_fyy[i];
    if (do_epi) {
        fxx = 0.5f * fxx - 0.5f * __logf(g_S0[i]);
        fyx = 0.5f * fyx - 0.5f * __logf(g_S1[i]);
        fxy = 0.5f * fxy - 0.5f * __logf(g_S2[i]);
        fyy = 0.5f * fyy - 0.5f * __logf(g_S3[i]);
        g_fxx[i] = fxx; g_fyx[i] = fyx; g_fxy[i] = fxy; g_fyy[i] = fyy;
    }
    g_S0[i] = 0.f; g_S2[i] = 0.f; g_S3[i] = 0.f;
    g_w0[i] = __expf(a[i] + fxx);    // Hxx sym GEMV
    g_w1[i] = __expf(a[i] + fxy);    // Hyx row GEMV (OLD fxy)
    g_w3[i] = __expf(bw[i] + fyy);   // Hyy sym GEMV
}

// Fused GEMV. blockIdx.x:
//  [0, 272)      : Hxx symmetric tile-pairs -> S0 (atomic)
//  [272, 544)    : Hyy symmetric tile-pairs -> S3 (atomic)
//  [544, 800)    : Hyx row GEMV (8 rows/block) -> S1 raw
__global__ __launch_bounds__(256) void k_gemv() {
    __shared__ union {
        struct { __half tile[2][64][72]; float wI[64]; float wJ[128]; } s;
        float ws[NN];
    } sm;
    int bz = blockIdx.z;
    int bx = blockIdx.x;
    int tid = threadIdx.x;

    if (bx < 2 * NGRP) {
        // ---- symmetric tile-pair GEMV ----
        int sel = bx >= NGRP;
        int gid = bx - sel * NGRP;
        // decode gid -> (I, J0): groups per row I = ceil((I+1)/2)
        int I = 0, base = 0;
        for (;;) {
            int ng = (I + 2) >> 1;
            if (gid < base + ng) break;
            base += ng;
            I++;
        }
        int J0 = (gid - base) * 2;
        int nt = (J0 + 1 <= I) ? 2 : 1;
        int t0 = I * (I + 1) / 2 + J0;

        const __half* Hb = (sel ? g_Hyy : g_Hxx) + ((size_t)bz * SYMT + t0) * TILE_ELEMS;
        const float* w = sel ? g_w3 : g_w0;
        float* S = (sel ? g_S3 : g_S0) + bz * NN;

        // load nt contiguous 8KB tiles (16KB max), 4 uint4/thread, MLP=4
        const uint4* Hv = (const uint4*)Hb;
        int nvec = nt * 512;
#pragma unroll
        for (int i = 0; i < 4; i++) {
            int idx = tid + i * 256;
            if (idx < nvec) {
                int k = idx >> 9, rr = (idx >> 3) & 63, cc = (idx & 7) * 8;
                *(uint4*)&sm.s.tile[k][rr][cc] = Hv[idx];
            }
        }
        if (tid < 64) sm.s.wI[tid] = w[bz * NN + I * 64 + tid];
        else if (tid < 192) sm.s.wJ[tid - 64] = w[bz * NN + J0 * 64 + tid - 64];
        __syncthreads();

        // row product: S[I*64+r] += sum over tiles k, cols c: tile[k][r][c]*wJ[k*64+c]
        {
            int r = tid >> 2, q = tid & 3;
            float acc = 0.f;
#pragma unroll
            for (int k = 0; k < 2; k++) {
                if (k < nt) {
                    const __half2* trow = (const __half2*)&sm.s.tile[k][r][q * 16];
                    const float* wj = &sm.s.wJ[k * 64 + q * 16];
#pragma unroll
                    for (int i = 0; i < 8; i++) {
                        float2 h = __half22float2(trow[i]);
                        acc = fmaf(h.x, wj[2 * i], acc);
                        acc = fmaf(h.y, wj[2 * i + 1], acc);
                    }
                }
            }
            acc += __shfl_xor_sync(0xffffffffu, acc, 1);
            acc += __shfl_xor_sync(0xffffffffu, acc, 2);
            if (q == 0) atomicAdd(&S[I * 64 + r], acc);
        }
        // column products (off-diagonal tiles): S[J*64+c] += sum_r tile[k][r][c]*wI[r]
        {
            int p = tid >> 6, c = tid & 63;
#pragma unroll
            for (int k = 0; k < 2; k++) {
                int J = J0 + k;
                if (k < nt && J != I) {
                    float cacc = 0.f;
#pragma unroll
                    for (int i = 0; i < 16; i++) {
                        int r = p * 16 + i;
                        cacc = fmaf(__half2float(sm.s.tile[k][r][c]), sm.s.wI[r], cacc);
                    }
                    atomicAdd(&S[J * 64 + c], cacc);
                }
            }
        }
    } else {
        // ---- Hyx row GEMV: 8 rows/block, w1 staged in SMEM ----
        int rloc = (bx - 2 * NGRP) * 8;
        const float4* wg = (const float4*)(g_w1 + bz * NN);
        float4* wsv = (float4*)sm.ws;
#pragma unroll
        for (int i = 0; i < 2; i++) wsv[i * 256 + tid] = wg[i * 256 + tid];
        __syncthreads();

        int warp = tid >> 5, lane = tid & 31;
        int row = rloc + warp;
        const uint4* hrow = (const uint4*)(g_Hyx + ((size_t)bz * NN + row) * NN);
        float acc0 = 0.f, acc1 = 0.f;
#pragma unroll
        for (int it = 0; it < 8; it++) {
            uint4 h = hrow[it * 32 + lane];
            const float* wp = &sm.ws[(it * 32 + lane) * 8];
            float4 wa = *(const float4*)wp;
            float4 wb = *(const float4*)(wp + 4);
            float2 h0 = __half22float2(*(const __half2*)&h.x);
            float2 h1 = __half22float2(*(const __half2*)&h.y);
            float2 h2 = __half22float2(*(const __half2*)&h.z);
            float2 h3 = __half22float2(*(const __half2*)&h.w);
            acc0 = fmaf(h0.x, wa.x, acc0);
            acc1 = fmaf(h0.y, wa.y, acc1);
            acc0 = fmaf(h1.x, wa.z, acc0);
            acc1 = fmaf(h1.y, wa.w, acc1);
            acc0 = fmaf(h2.x, wb.x, acc0);
            acc1 = fmaf(h2.y, wb.y, acc1);
            acc0 = fmaf(h3.x, wb.z, acc0);
            acc1 = fmaf(h3.y, wb.w, acc1);
        }
        float acc = acc0 + acc1;
#pragma unroll
        for (int o = 16; o; o >>= 1) acc += __shfl_xor_sync(0xffffffffu, acc, o);
        if (lane == 0) g_S1[bz * NN + row] = acc;   // raw; epilogue deferred
    }
}

// Column GEMV over g_Hyx: S2[b,l] += sum_k Hyx[b,k,l]*w2[b,k].
// Gauss-Seidel: w2 uses NEW fyx, recomputed locally from raw S1.
// k-split 64 (512 blocks) for occupancy.
__global__ __launch_bounds__(256) void k_gemv_cols(const float* __restrict__ bw, int fin) {
    __shared__ float ws[32];
    int b = blockIdx.z, ks = blockIdx.x;
    int tid = threadIdx.x;
    if (tid < 32) {
        int k = b * NN + ks * 32 + tid;
        float fyx = g_fyx[k];
        if (!fin) fyx = 0.5f * fyx - 0.5f * __logf(g_S1[k]);
        ws[tid] = __expf(bw[k] + fyx);
    }
    __syncthreads();

    const uint4* Hb = (const uint4*)(g_Hyx + ((size_t)b * NN + ks * 32) * NN);
    float acc[8];
#pragma unroll
    for (int j = 0; j < 8; j++) acc[j] = 0.f;
#pragma unroll 4
    for (int k = 0; k < 32; k++) {
        float wk = ws[k];
        uint4 h = Hb[(size_t)k * (NN / 8) + tid];
        float2 h0 = __half22float2(*(const __half2*)&h.x);
        float2 h1 = __half22float2(*(const __half2*)&h.y);
        float2 h2 = __half22float2(*(const __half2*)&h.z);
        float2 h3 = __half22float2(*(const __half2*)&h.w);
        acc[0] = fmaf(h0.x, wk, acc[0]);
        acc[1] = fmaf(h0.y, wk, acc[1]);
        acc[2] = fmaf(h1.x, wk, acc[2]);
        acc[3] = fmaf(h1.y, wk, acc[3]);
        acc[4] = fmaf(h2.x, wk, acc[4]);
        acc[5] = fmaf(h2.y, wk, acc[5]);
        acc[6] = fmaf(h3.x, wk, acc[6]);
        acc[7] = fmaf(h3.y, wk, acc[7]);
    }
    float* S = g_S2 + b * NN + 8 * tid;
#pragma unroll
    for (int j = 0; j < 8; j++) atomicAdd(S + j, acc[j]);
}

// res[b] = sum_l (fe_xy - fe_xx) e^a + sum_k (fe_yx - fe_yy) e^b, fe_* = -log S_*.
__global__ __launch_bounds__(256) void k_reduce(const float* __restrict__ a,
                                                const float* __restrict__ bw,
                                                float* __restrict__ out) {
    int b = blockIdx.x;
    float acc = 0.f;
    for (int i = threadIdx.x; i < NN; i += 256) {
        int idx = b * NN + i;
        float fexx = -__logf(g_S0[idx]);
        float feyx = -__logf(g_S1[idx]);
        float fexy = -__logf(g_S2[idx]);
        float feyy = -__logf(g_S3[idx]);
        acc += (fexy - fexx) * __expf(a[idx]) + (feyx - feyy) * __expf(bw[idx]);
    }
    __shared__ float red[256];
    red[threadIdx.x] = acc;
    __syncthreads();
    for (int s = 128; s; s >>= 1) {
        if (threadIdx.x < s) red[threadIdx.x] += red[threadIdx.x + s];
        __syncthreads();
    }
    if (threadIdx.x == 0) out[b] = red[0];
}

// ---------------- launch ----------------
extern "C" void kernel_launch(void* const* d_in, const int* in_sizes, int n_in,
                              void* d_out, int out_size) {
    const float* x = (const float*)d_in[0];
    const float* a = (const float*)d_in[1];
    const float* y = (const float*)d_in[2];
    const float* b = (const float*)d_in[3];
    float* out = (float*)d_out;

    const int SMALL_BLOCKS = TOT / 256;
    dim3 buildGrid(NTILES, NTILES, BB);
    dim3 gemvGrid(2 * NGRP + 256, 1, BB);   // (800, 1, 8)
    dim3 colsGrid(64, 1, BB);               // 512 blocks

    k_norms<<<SMALL_BLOCKS, 256>>>(x, y);

    k_build<<<buildGrid, 256>>>(0, 1, x, x, 0, 0);   // Hxx tiled lower-tri
    k_build<<<buildGrid, 256>>>(1, 0, y, x, 1, 0);   // Hyx full row-major
    k_build<<<buildGrid, 256>>>(2, 1, y, y, 1, 1);   // Hyy tiled lower-tri

    for (int it = 0; it <= 10; it++) {
        int fin = (it == 10);
        k_prep<<<SMALL_BLOCKS, 256>>>(a, b, it > 0);
        k_gemv<<<gemvGrid, 256>>>();
        k_gemv_cols<<<colsGrid, 256>>>(b, fin);
    }

    k_reduce<<<BB, 256>>>(a, b, out);
}

// round 7
// speedup vs baseline: 1.0980x; 1.0523x over previous
#include <cuda_runtime.h>
#include <cuda_fp16.h>

// Problem constants: B=8, L=K=2048, D=32, SIGMA=1, EPS=1, 10 iters.
#define BB 8
#define NN 2048
#define DD 32
#define TOT (BB * NN)
#define MAT_ELEMS ((size_t)BB * NN * NN)

#define H2(u) (*(const __half2*)&(u))

// ---------------- device scratch ----------------
static __device__ __half g_Hxx[MAT_ELEMS];   // full row-major fp16 (symmetric content)
static __device__ __half g_Hyx[MAT_ELEMS];   // full, rows = y index
static __device__ __half g_Hyy[MAT_ELEMS];   // full row-major fp16 (symmetric content)
static __device__ float g_nx[TOT], g_ny[TOT];
static __device__ float g_fxx[TOT], g_fyx[TOT], g_fxy[TOT], g_fyy[TOT];
static __device__ __half g_w0h[TOT], g_w1h[TOT], g_w3h[TOT];
static __device__ float g_S0[TOT], g_S1[TOT], g_S2[TOT], g_S3[TOT];

// ---------------- kernels ----------------

__global__ __launch_bounds__(256) void k_norms(const float* __restrict__ x,
                                               const float* __restrict__ y) {
    int i = blockIdx.x * 256 + threadIdx.x;
    if (i >= TOT) return;
    const float* xr = x + (size_t)i * DD;
    const float* yr = y + (size_t)i * DD;
    float sx = 0.f, sy = 0.f;
#pragma unroll
    for (int d = 0; d < DD; d++) {
        sx = fmaf(xr[d], xr[d], sx);
        sy = fmaf(yr[d], yr[d], sy);
    }
    g_nx[i] = sx;
    g_ny[i] = sy;
    g_fxx[i] = 0.f; g_fyx[i] = 0.f; g_fxy[i] = 0.f; g_fyy[i] = 0.f;
}

// Build H[b][r][c] = exp(exp(-max(nr+nc-2*dot,0)/2)), fp16, full row-major.
// sym!=0: compute lower-triangle blocks only; mirror tile written via SMEM
// transpose (coalesced).
__global__ __launch_bounds__(256) void k_build(int hsel, int sym,
                                               const float* __restrict__ Rm,
                                               const float* __restrict__ Cm,
                                               int rn, int cn) {
    int bx = blockIdx.x, by = blockIdx.y, b = blockIdx.z;
    if (sym && bx > by) return;
    __shared__ float srt[DD][68];
    __shared__ float sct[DD][68];
    __shared__ __half stile[64][72];

    int r0 = by * 64, c0 = bx * 64;
    const float* Rb = Rm + ((size_t)b * NN + r0) * DD;
    const float* Cb = Cm + ((size_t)b * NN + c0) * DD;
    for (int i = threadIdx.x; i < 64 * DD; i += 256) {
        int row = i >> 5, d = i & 31;
        srt[d][row] = Rb[i];
        sct[d][row] = Cb[i];
    }
    __syncthreads();

    int tx = threadIdx.x & 15, ty = threadIdx.x >> 4;
    float acc[4][4];
#pragma unroll
    for (int i = 0; i < 4; i++)
#pragma unroll
        for (int j = 0; j < 4; j++) acc[i][j] = 0.f;

#pragma unroll
    for (int d = 0; d < DD; d++) {
        float4 rv4 = *(const float4*)&srt[d][ty * 4];
        float4 cv4 = *(const float4*)&sct[d][tx * 4];
        float rv[4] = {rv4.x, rv4.y, rv4.z, rv4.w};
        float cv[4] = {cv4.x, cv4.y, cv4.z, cv4.w};
#pragma unroll
        for (int i = 0; i < 4; i++)
#pragma unroll
            for (int j = 0; j < 4; j++)
                acc[i][j] = fmaf(rv[i], cv[j], acc[i][j]);
    }

    const float* nRp = (rn ? g_ny : g_nx) + b * NN + r0;
    const float* nCp = (cn ? g_ny : g_nx) + b * NN + c0;
    float nr[4], ncv[4];
#pragma unroll
    for (int i = 0; i < 4; i++) nr[i] = nRp[ty * 4 + i];
#pragma unroll
    for (int j = 0; j < 4; j++) ncv[j] = nCp[tx * 4 + j];

    __half* H = (hsel == 0 ? g_Hxx : hsel == 1 ? g_Hyx : g_Hyy);
    bool mirror = sym && (bx != by);
#pragma unroll
    for (int i = 0; i < 4; i++) {
        float o[4];
#pragma unroll
        for (int j = 0; j < 4; j++) {
            float dist = nr[i] + ncv[j] - 2.f * acc[i][j];
            float t = __expf(-0.5f * fmaxf(dist, 0.f));
            o[j] = __expf(t);
        }
        union { __half2 h2[2]; uint2 u; } cv;
        cv.h2[0] = __floats2half2_rn(o[0], o[1]);
        cv.h2[1] = __floats2half2_rn(o[2], o[3]);
        *(uint2*)&H[((size_t)b * NN + r0 + ty * 4 + i) * NN + c0 + tx * 4] = cv.u;
        if (mirror) *(uint2*)&stile[ty * 4 + i][tx * 4] = cv.u;
    }
    if (mirror) {
        __syncthreads();
#pragma unroll
        for (int i = 0; i < 4; i++) {
            int mr = ty * 4 + i;
            __half v[4];
#pragma unroll
            for (int j = 0; j < 4; j++) v[j] = stile[tx * 4 + j][mr];
            *(uint2*)&H[((size_t)b * NN + c0 + mr) * NN + r0 + tx * 4] = *(uint2*)v;
        }
    }
}

// Per-iteration prep: deferred fxy epilogue (from prev cols pass), zero S2,
// fp16 weight vectors.
__global__ __launch_bounds__(256) void k_prep(const float* __restrict__ a,
                                              const float* __restrict__ bw,
                                              int do_epi) {
    int i = blockIdx.x * 256 + threadIdx.x;
    if (i >= TOT) return;
    float fxy = g_fxy[i];
    if (do_epi) {
        fxy = 0.5f * fxy - 0.5f * __logf(g_S2[i]);
        g_fxy[i] = fxy;
    }
    g_S2[i] = 0.f;
    g_w0h[i] = __float2half(__expf(a[i] + g_fxx[i]));   // Hxx rows
    g_w1h[i] = __float2half(__expf(a[i] + fxy));        // Hyx rows (OLD fxy)
    g_w3h[i] = __float2half(__expf(bw[i] + g_fyy[i]));  // Hyy rows
}

// Row GEMV over the three matrices (blockIdx.y = sel). One warp per row,
// fp16 w staged in SMEM, HFMA2 inner loop, fp32 accumulate every 32B.
// final_mode=0: f = 0.5 f - 0.5 log(S) in-place.  final_mode=1: store raw S.
__global__ __launch_bounds__(256) void k_gemv_rows(int final_mode) {
    __shared__ __half wsh[NN];      // 4 KB
    int sel = blockIdx.y;           // 0: Hxx/w0/fxx/S0, 1: Hyy/w3/fyy/S3, 2: Hyx/w1/fyx/S1
    int bz = blockIdx.z;
    const __half* H = sel == 0 ? g_Hxx : sel == 1 ? g_Hyy : g_Hyx;
    const __half* w = sel == 0 ? g_w0h : sel == 1 ? g_w3h : g_w1h;
    float* f = sel == 0 ? g_fxx : sel == 1 ? g_fyy : g_fyx;
    float* S = sel == 0 ? g_S0 : sel == 1 ? g_S3 : g_S1;

    int tid = threadIdx.x;
    ((uint4*)wsh)[tid] = ((const uint4*)(w + bz * NN))[tid];   // 256 x 16B = 4KB
    __syncthreads();

    int warp = tid >> 5, lane = tid & 31;
    int row = blockIdx.x * 8 + warp;
    const uint4* hrow = (const uint4*)(H + ((size_t)bz * NN + row) * NN);
    const uint4* wv = (const uint4*)wsh;

    float accx = 0.f, accy = 0.f;
#pragma unroll
    for (int it = 0; it < 4; it++) {
        uint4 h0 = hrow[(2 * it) * 32 + lane];
        uint4 h1 = hrow[(2 * it + 1) * 32 + lane];
        uint4 w0 = wv[(2 * it) * 32 + lane];
        uint4 w1 = wv[(2 * it + 1) * 32 + lane];
        __half2 p = __hmul2(H2(h0.x), H2(w0.x));
        __half2 q = __hmul2(H2(h1.x), H2(w1.x));
        p = __hfma2(H2(h0.y), H2(w0.y), p);
        q = __hfma2(H2(h1.y), H2(w1.y), q);
        p = __hfma2(H2(h0.z), H2(w0.z), p);
        q = __hfma2(H2(h1.z), H2(w1.z), q);
        p = __hfma2(H2(h0.w), H2(w0.w), p);
        q = __hfma2(H2(h1.w), H2(w1.w), q);
        float2 fp = __half22float2(p);
        float2 fq = __half22float2(q);
        accx += fp.x + fq.x;
        accy += fp.y + fq.y;
    }
    float acc = accx + accy;
#pragma unroll
    for (int o = 16; o; o >>= 1) acc += __shfl_xor_sync(0xffffffffu, acc, o);
    if (lane == 0) {
        if (final_mode) S[row + bz * NN] = acc;
        else            f[row + bz * NN] = 0.5f * f[row + bz * NN] - 0.5f * __logf(acc);
    }
}

// Column GEMV over g_Hyx: S2[b,l] += sum_k Hyx[b,k,l] * exp(b[k] + fyx[k]).
// fyx already holds the NEW value (rows pass applied epilogue in-place);
// final iteration leaves fyx untouched, which is exactly what's needed.
// grid (64 k-splits, 1, B); thread owns 8 consecutive columns; HFMA2 inner
// loop, flush to fp32 every 8 k.
__global__ __launch_bounds__(256) void k_gemv_cols(const float* __restrict__ bw) {
    __shared__ __half2 ws2[32];
    int b = blockIdx.z, ks = blockIdx.x;
    int tid = threadIdx.x;
    if (tid < 32) {
        int k = b * NN + ks * 32 + tid;
        ws2[tid] = __half2half2(__float2half(__expf(bw[k] + g_fyx[k])));
    }
    __syncthreads();

    const uint4* Hb = (const uint4*)(g_Hyx + ((size_t)b * NN + ks * 32) * NN);
    float facc[8];
#pragma unroll
    for (int j = 0; j < 8; j++) facc[j] = 0.f;

#pragma unroll
    for (int kb = 0; kb < 4; kb++) {
        __half2 a0 = __float2half2_rn(0.f), a1 = a0, a2 = a0, a3 = a0;
#pragma unroll
        for (int k = 0; k < 8; k++) {
            __half2 wk = ws2[kb * 8 + k];
            uint4 h = Hb[(size_t)(kb * 8 + k) * 256 + tid];
            a0 = __hfma2(H2(h.x), wk, a0);
            a1 = __hfma2(H2(h.y), wk, a1);
            a2 = __hfma2(H2(h.z), wk, a2);
            a3 = __hfma2(H2(h.w), wk, a3);
        }
        float2 t0 = __half22float2(a0);
        float2 t1 = __half22float2(a1);
        float2 t2 = __half22float2(a2);
        float2 t3 = __half22float2(a3);
        facc[0] += t0.x; facc[1] += t0.y;
        facc[2] += t1.x; facc[3] += t1.y;
        facc[4] += t2.x; facc[5] += t2.y;
        facc[6] += t3.x; facc[7] += t3.y;
    }
    float* S = g_S2 + b * NN + 8 * tid;
#pragma unroll
    for (int j = 0; j < 8; j++) atomicAdd(S + j, facc[j]);
}

// res[b] = sum_l (fe_xy - fe_xx) e^a + sum_k (fe_yx - fe_yy) e^b, fe_* = -log S_*.
__global__ __launch_bounds__(256) void k_reduce(const float* __restrict__ a,
                                                const float* __restrict__ bw,
                                                float* __restrict__ out) {
    int b = blockIdx.x;
    float acc = 0.f;
    for (int i = threadIdx.x; i < NN; i += 256) {
        int idx = b * NN + i;
        float fexx = -__logf(g_S0[idx]);
        float feyx = -__logf(g_S1[idx]);
        float fexy = -__logf(g_S2[idx]);
        float feyy = -__logf(g_S3[idx]);
        acc += (fexy - fexx) * __expf(a[idx]) + (feyx - feyy) * __expf(bw[idx]);
    }
    __shared__ float red[256];
    red[threadIdx.x] = acc;
    __syncthreads();
    for (int s = 128; s; s >>= 1) {
        if (threadIdx.x < s) red[threadIdx.x] += red[threadIdx.x + s];
        __syncthreads();
    }
    if (threadIdx.x == 0) out[b] = red[0];
}

// ---------------- launch ----------------
extern "C" void kernel_launch(void* const* d_in, const int* in_sizes, int n_in,
                              void* d_out, int out_size) {
    const float* x = (const float*)d_in[0];
    const float* a = (const float*)d_in[1];
    const float* y = (const float*)d_in[2];
    const float* b = (const float*)d_in[3];
    float* out = (float*)d_out;

    const int SMALL_BLOCKS = TOT / 256;        // 64
    dim3 buildGrid(NN / 64, NN / 64, BB);      // (32, 32, 8)
    dim3 rowsGrid(NN / 8, 3, BB);              // (256, 3, 8)
    dim3 colsGrid(64, 1, BB);                  // 512 blocks

    k_norms<<<SMALL_BLOCKS, 256>>>(x, y);

    k_build<<<buildGrid, 256>>>(0, 1, x, x, 0, 0);   // Hxx (sym, mirrored)
    k_build<<<buildGrid, 256>>>(1, 0, y, x, 1, 0);   // Hyx full
    k_build<<<buildGrid, 256>>>(2, 1, y, y, 1, 1);   // Hyy (sym, mirrored)

    // iters 0..9: Sinkhorn; iter 10: final extrapolation (raw sums).
    for (int it = 0; it <= 10; it++) {
        int fin = (it == 10);
        k_prep<<<SMALL_BLOCKS, 256>>>(a, b, it > 0);
        k_gemv_rows<<<rowsGrid, 256>>>(fin);
        k_gemv_cols<<<colsGrid, 256>>>(b);
    }

    k_reduce<<<BB, 256>>>(a, b, out);
}